// round 16
// baseline (speedup 1.0000x reference)
#include <cuda_runtime.h>
#include <cuda_bf16.h>
#include <cstdint>
#include <math.h>

#define Bc 64
#define Tc 512
#define Ic 512
#define Hc 512
#define Oc 512

// Scratch
__device__ uint32_t g_z16 [(long)Bc * Tc * Hc / 2];  // z (bf16x2)
__device__ uint32_t g_x16 [(long)Bc * Tc * Ic / 2];  // x as bf16x2
__device__ uint32_t g_zr16[(long)Bc * Tc * Hc / 2];  // zr (bf16x2)
__device__ uint32_t g_hn16[(long)Bc * Tc * Hc / 2];  // h_new (bf16x2)
__device__ float    g_hpr[Bc * Hc];
__device__ float    g_hpz[Bc * Hc];
__device__ __nv_bfloat16 g_WT16[5l * 512 * 512];     // W^T bf16 [sel][n][k]
// slabs: 0=Wr_x 1=Wz_x 2=Wh_x 3=Wh_h 4=Wo

__device__ __forceinline__ float sigmoidf_(float x) { return 1.0f / (1.0f + expf(-x)); }

__device__ __forceinline__ uint32_t pk(float lo, float hi) {
    __nv_bfloat162 h = __floats2bfloat162_rn(lo, hi);
    return *reinterpret_cast<uint32_t*>(&h);
}
__device__ __forceinline__ float2 upk(uint32_t u) {
    __nv_bfloat162 h = *reinterpret_cast<__nv_bfloat162*>(&u);
    return __bfloat1622float2(h);
}

__device__ __forceinline__ uint32_t smem_u32(const void* p) {
    uint32_t a;
    asm("{ .reg .u64 t; cvta.to.shared.u64 t, %1; cvt.u32.u64 %0, t; }" : "=r"(a) : "l"(p));
    return a;
}

__device__ __forceinline__ void gdc_wait()   { asm volatile("griddepcontrol.wait;" ::: "memory"); }
__device__ __forceinline__ void gdc_launch() { asm volatile("griddepcontrol.launch_dependents;" ::: "memory"); }

__device__ __forceinline__ void mma_bf16(float* c, const uint32_t* a, const uint32_t* b) {
    asm volatile(
        "mma.sync.aligned.m16n8k16.row.col.f32.bf16.bf16.f32 "
        "{%0,%1,%2,%3}, {%4,%5,%6,%7}, {%8,%9}, {%0,%1,%2,%3};"
        : "+f"(c[0]), "+f"(c[1]), "+f"(c[2]), "+f"(c[3])
        : "r"(a[0]), "r"(a[1]), "r"(a[2]), "r"(a[3]), "r"(b[0]), "r"(b[1]));
}

__device__ __forceinline__ void ldm4(uint32_t* r, uint32_t addr) {
    asm volatile("ldmatrix.sync.aligned.m8n8.x4.shared.b16 {%0,%1,%2,%3}, [%4];"
                 : "=r"(r[0]), "=r"(r[1]), "=r"(r[2]), "=r"(r[3]) : "r"(addr));
}

#define CP16(saddr, gptr) asm volatile("cp.async.cg.shared.global [%0], [%1], 16;" :: "r"(saddr), "l"(gptr))
#define CP_COMMIT()       asm volatile("cp.async.commit_group;" ::: "memory")
#define CP_WAIT1()        asm volatile("cp.async.wait_group 1;" ::: "memory")
#define CP_WAIT0()        asm volatile("cp.async.wait_group 0;" ::: "memory")

#define PITCH 36
#define ROWPB (PITCH * 4)                 // 144 bytes per row
#define STGB  (256u * ROWPB)              // bytes per stage (36864), all modes
#define WSLAB 524288                      // bytes per weight slab in g_WT16

// ---------------------------------------------------------------------------
// bf16 mma.sync GEMM (R13 engine). ALL modes: 256 thr, 8 warps (4M x 2N),
// 2 CTAs/SM, CTA 128M x 128 B-rows per tile, BK=64, cp.async 3-stage,
// ldmatrix x4. PDL overlap at kernel boundaries.
// MODE 0/2: persistent 2-tile CTAs (two stacked M-tiles, grid.y halved);
//   the pipeline runs continuously across the tile boundary, mid-loop
//   epilogue hidden under in-flight DMA. B offsets identical across tiles.
// MODE 1: single tile, K=1024 ([zr|x] @ [Wh_h;Wh_x]).
// ---------------------------------------------------------------------------
template <int MODE>
__global__ __launch_bounds__(256, 2)
void kgemm(float* __restrict__ Cout, const float* __restrict__ bias,
           const float* __restrict__ h0, int Nt, int Tfull)
{
    constexpr int CHUNKS = (MODE == 1) ? 16 : 8;
    constexpr int TILES  = (MODE == 1) ? 1 : 2;
    constexpr int TOTAL  = TILES * CHUNKS;
    constexpr int W      = (MODE == 0) ? 2 : 1;
    constexpr int NT     = (MODE == 0) ? 4 : 8;
    constexpr int NTILE  = (MODE == 0) ? 64 : 128;
    constexpr int WNW    = (MODE == 0) ? 32 : 64;

    extern __shared__ uint32_t sm[];
    const uint32_t sbase = smem_u32(sm);

    const int tid = threadIdx.x;
    const int wid = tid >> 5, lid = tid & 31;
    const int g = lid >> 2, t = lid & 3;
    const int warpM = wid & 3;
    const int warpN = wid >> 2;
    const int m0 = blockIdx.y * (128 * TILES);
    const int n0 = blockIdx.x * NTILE;

    const char* xb  = (const char*)g_x16;
    const char* zrb = (const char*)g_zr16;
    const char* hnb = (const char*)g_hn16;
    const char* wtb = (const char*)g_WT16;

    // ---- per-slot byte offsets ----
    uint32_t offA[TILES][4];     // A offsets per tile (bf16 rows, 1024 B/row)
    uint32_t offX[4];            // MODE 1: x offsets for kt>=8
    uint32_t offB[4];            // B offsets (within slab / slab0-based for MODE 0)
    uint32_t sofA[4], sofB[4];
#pragma unroll
    for (int i = 0; i < 4; i++) {
        int c = tid + 256 * i;
        int row = c >> 3, q = c & 7;
        sofA[i] = (uint32_t)row * ROWPB + q * 16;
#pragma unroll
        for (int tl = 0; tl < TILES; tl++) {
            int gm = m0 + tl * 128 + row;
            uint32_t xoff = (uint32_t)((long)(gm / Nt) * Tfull + (gm % Nt)) * 1024u + q * 16;
            if (MODE == 0) offA[tl][i] = xoff;
            else           offA[tl][i] = (uint32_t)gm * 1024u + q * 16;
            if (MODE == 1 && tl == 0) offX[i] = xoff;
        }
        // B slot
        int brow = row, qb = q;
        if (MODE == 0) {
            int sel = brow >> 6, nr = brow & 63;
            offB[i] = (uint32_t)sel * WSLAB + (uint32_t)(n0 + nr) * 1024u + qb * 16;
        } else {
            offB[i] = (uint32_t)(n0 + brow) * 1024u + qb * 16;
        }
        sofB[i] = (uint32_t)(128 + brow) * ROWPB + qb * 16;
    }

    const uint32_t a_addr = sbase + (uint32_t)(warpM * 32 + (lid & 15)) * ROWPB
                          + ((lid & 16) ? 16 : 0);
    const int b_row = ((lid & 16) ? 8 : 0) + (lid & 7);
    const uint32_t b_addr = sbase + (uint32_t)(128 + b_row) * ROWPB + ((lid & 8) ? 16 : 0);

    uint32_t bgrp_off[4];
#pragma unroll
    for (int gb = 0; gb < 4; gb++) {
        int base = (MODE == 0) ? ((gb >> 1) * 64 + warpN * 32 + (gb & 1) * 16)
                               : (warpN * 64 + gb * 16);
        bgrp_off[gb] = (uint32_t)base * ROWPB;
    }

    float c[W][2][NT][4];
#pragma unroll
    for (int w = 0; w < W; w++)
#pragma unroll
        for (int mt = 0; mt < 2; mt++)
#pragma unroll
            for (int nt = 0; nt < NT; nt++)
#pragma unroll
                for (int q = 0; q < 4; q++) c[w][mt][nt][q] = 0.0f;

    // ---- cp.async: A slot i for global chunk cc ----
    auto issueA = [&](int i, int cc, uint32_t stb) {
        const int tl = cc / CHUNKS;
        const int kt = cc - tl * CHUNKS;
        const char* src;
        if (MODE == 0) {
            src = xb + offA[tl][i] + kt * 128;
        } else if (MODE == 1) {
            src = (kt < 8) ? (zrb + offA[0][i] + kt * 128)
                           : (xb + offX[i] + (kt - 8) * 128);
        } else {
            src = hnb + offA[tl][i] + kt * 128;
        }
        CP16(sbase + stb + sofA[i], src);
    };
    // ---- cp.async: B slot i for global chunk cc (tile-independent) ----
    auto issueB = [&](int i, int cc, uint32_t stb) {
        const int kt = cc % CHUNKS;
        const char* src;
        if (MODE == 0)      src = wtb + offB[i] + kt * 128;
        else if (MODE == 1) src = wtb + offB[i] + ((kt < 8) ? 3u : 2u) * WSLAB + (kt & 7) * 128;
        else                src = wtb + offB[i] + 4u * WSLAB + kt * 128;
        CP16(sbase + stb + sofB[i], src);
    };

    // ---- epilogue for one tile ----
    auto epilogue = [&](int tl) {
        const int mb = m0 + tl * 128;
#pragma unroll
        for (int mt = 0; mt < 2; mt++) {
#pragma unroll
            for (int rh = 0; rh < 2; rh++) {
                const int m = mb + warpM * 32 + mt * 16 + g + rh * 8;
                const int b = m / Nt;
#pragma unroll
                for (int nt = 0; nt < NT; nt++) {
                    const int n = n0 + warpN * WNW + nt * 8 + t * 2;
                    const long hidx = (long)m * 256 + (n >> 1);
                    if (MODE == 0) {
                        float vr0 = c[0][mt][nt][rh * 2 + 0], vr1 = c[0][mt][nt][rh * 2 + 1];
                        float vz0 = c[1 % W][mt][nt][rh * 2 + 0], vz1 = c[1 % W][mt][nt][rh * 2 + 1];
                        float r0 = sigmoidf_(vr0 + g_hpr[b * 512 + n]);
                        float r1 = sigmoidf_(vr1 + g_hpr[b * 512 + n + 1]);
                        float z0 = sigmoidf_(vz0 + g_hpz[b * 512 + n]);
                        float z1 = sigmoidf_(vz1 + g_hpz[b * 512 + n + 1]);
                        g_zr16[hidx] = pk(z0 * r0, z1 * r1);
                        g_z16[hidx]  = pk(z0, z1);
                    } else if (MODE == 1) {
                        float v0 = c[0][mt][nt][rh * 2 + 0], v1 = c[0][mt][nt][rh * 2 + 1];
                        float2 zv = upk(g_z16[hidx]);
                        float2 hv = *(const float2*)(h0 + b * 512 + n);
                        float2 bv = *(const float2*)(bias + n);
                        float o0 = (1.0f - zv.x) * hv.x + zv.x * tanhf(v0 + bv.x);
                        float o1 = (1.0f - zv.y) * hv.y + zv.y * tanhf(v1 + bv.y);
                        g_hn16[hidx] = pk(o0, o1);
                    } else {
                        float v0 = c[0][mt][nt][rh * 2 + 0], v1 = c[0][mt][nt][rh * 2 + 1];
                        float2 bv = *(const float2*)(bias + n);
                        *(float2*)(Cout + (long)m * 512 + n) =
                            make_float2(sigmoidf_(v0 + bv.x), sigmoidf_(v1 + bv.y));
                    }
                }
            }
        }
    };

    // ---- prologue with PDL overlap ----
    if (MODE == 0) {
        gdc_wait();
#pragma unroll
        for (int i = 0; i < 4; i++) issueA(i, 0, 0);
#pragma unroll
        for (int i = 0; i < 4; i++) issueB(i, 0, 0);
        CP_COMMIT();
#pragma unroll
        for (int i = 0; i < 4; i++) issueA(i, 1, STGB);
#pragma unroll
        for (int i = 0; i < 4; i++) issueB(i, 1, STGB);
        CP_COMMIT();
    } else {
        // Weights are >=2 PDL hops upstream: prefetch B pre-wait.
#pragma unroll
        for (int i = 0; i < 4; i++) issueB(i, 0, 0);
#pragma unroll
        for (int i = 0; i < 4; i++) issueB(i, 1, STGB);
        gdc_wait();
#pragma unroll
        for (int i = 0; i < 4; i++) issueA(i, 0, 0);
        CP_COMMIT();          // group0 = {B ch0, B ch1, A ch0}
#pragma unroll
        for (int i = 0; i < 4; i++) issueA(i, 1, STGB);
        CP_COMMIT();          // group1 = {A ch1}
    }
    CP_WAIT1();
    __syncthreads();

    // ---- mainloop over TOTAL chunks (pipeline continuous across tiles) ----
    for (int cc = 0; cc < TOTAL; cc++) {
        const uint32_t stb = (uint32_t)(cc % 3) * STGB;
        const bool pf = (cc < TOTAL - 2);
        const uint32_t nstb = (uint32_t)((cc + 2) % 3) * STGB;

#pragma unroll
        for (int ks = 0; ks < 4; ks++) {
            if (pf) { issueA(ks, cc + 2, nstb); issueB(ks, cc + 2, nstb); }
            uint32_t af4[2][4];
#pragma unroll
            for (int mt = 0; mt < 2; mt++)
                ldm4(af4[mt], a_addr + stb + (uint32_t)mt * (16 * ROWPB) + ks * 32);
            uint32_t bf4[4][4];
#pragma unroll
            for (int gb = 0; gb < 4; gb++)
                ldm4(bf4[gb], b_addr + stb + bgrp_off[gb] + ks * 32);

            if (MODE == 0) {
#pragma unroll
                for (int w = 0; w < 2; w++)
#pragma unroll
                    for (int mt = 0; mt < 2; mt++)
#pragma unroll
                        for (int nt = 0; nt < NT; nt++)
                            mma_bf16(c[w % W][mt][nt], af4[mt],
                                     &bf4[w * 2 + (nt >> 1)][(nt & 1) * 2]);
            } else {
#pragma unroll
                for (int mt = 0; mt < 2; mt++)
#pragma unroll
                    for (int nt = 0; nt < NT; nt++)
                        mma_bf16(c[0][mt][nt], af4[mt], &bf4[nt >> 1][(nt & 1) * 2]);
            }
        }

        if (pf) CP_COMMIT();

        // Tile boundary: drain accums while next tile's DMA is in flight.
        if ((cc % CHUNKS) == CHUNKS - 1) {
            const int tl = cc / CHUNKS;
            if (cc == TOTAL - 1) gdc_launch();
            epilogue(tl);
            if (cc < TOTAL - 1) {
#pragma unroll
                for (int w = 0; w < W; w++)
#pragma unroll
                    for (int mt = 0; mt < 2; mt++)
#pragma unroll
                        for (int nt = 0; nt < NT; nt++)
#pragma unroll
                            for (int q = 0; q < 4; q++) c[w][mt][nt][q] = 0.0f;
            }
        }

        if (cc < TOTAL - 1) {
            if (pf) CP_WAIT1(); else CP_WAIT0();
            __syncthreads();
        }
    }
}

// ---------------------------------------------------------------------------
// Fused prep kernel: blockIdx.z selects work.
//   z = 0..4  : transpose+cvt weight sel z into g_WT16
//   z = 5     : hpart (g_hpr/g_hpz), first 128 of 256 blocks
//   z = 6     : copy h0 -> out tail (if h0dst != null), first 128 blocks
//   z >= 7    : x fp32 -> bf16x2 conversion
// ---------------------------------------------------------------------------
__global__ void prep_kernel(const float* __restrict__ Wr, const float* __restrict__ Wz,
                            const float* __restrict__ Wh, const float* __restrict__ Wo,
                            __nv_bfloat16* __restrict__ wdst,
                            const float* __restrict__ h0,
                            const float* __restrict__ br, const float* __restrict__ bz,
                            float* __restrict__ h0dst,
                            const float* __restrict__ x, uint32_t* __restrict__ x16,
                            long x4) {
    const int z = blockIdx.z;
    if (z < 5) {
        __shared__ float tbuf[32][33];
        const float* src = (z == 0) ? Wr : (z == 1) ? Wz : (z == 2) ? Wh
                         : (z == 3) ? (Wh + (long)Ic * Hc) : Wo;
        __nv_bfloat16* d = wdst + (long)z * 512 * 512;
        int bx = blockIdx.x * 32, by = blockIdx.y * 32;
#pragma unroll
        for (int i = 0; i < 4; i++)
            tbuf[threadIdx.y + i * 8][threadIdx.x] =
                src[(long)(by + threadIdx.y + i * 8) * 512 + bx + threadIdx.x];
        __syncthreads();
#pragma unroll
        for (int i = 0; i < 4; i++)
            d[(long)(bx + threadIdx.y + i * 8) * 512 + by + threadIdx.x] =
                __float2bfloat16(tbuf[threadIdx.x][threadIdx.y + i * 8]);
        gdc_launch();
        return;
    }
    const int tid = threadIdx.y * 32 + threadIdx.x;          // 0..255
    const int bid = blockIdx.y * 16 + blockIdx.x;            // 0..255
    if (z == 5) {
        if (bid < 128) {
            const int idx = bid * 256 + tid;
            const int b = idx >> 9, n = idx & 511;
            const float* Wr_h = Wr + (long)Ic * Hc;
            const float* Wz_h = Wz + (long)Ic * Hc;
            float ar = br[n], az = bz[n];
            const float* h0b = h0 + b * Hc;
            for (int k = 0; k < Hc; k++) {
                float h = h0b[k];
                ar = fmaf(h, Wr_h[k * Hc + n], ar);
                az = fmaf(h, Wz_h[k * Hc + n], az);
            }
            g_hpr[idx] = ar;
            g_hpz[idx] = az;
        }
    } else if (z == 6) {
        if (bid < 128 && h0dst) {
            const int idx = bid * 256 + tid;
            h0dst[idx] = h0[idx];
        }
    } else {
        const long base = ((long)(z - 7) * 256 + bid) * 1024;
#pragma unroll
        for (int it = 0; it < 4; it++) {
            long i = base + it * 256 + tid;
            if (i < x4) {
                float4 v = ((const float4*)x)[i];
                ((uint2*)x16)[i] = make_uint2(pk(v.x, v.y), pk(v.z, v.w));
            }
        }
    }
    gdc_launch();
}

// ---------------------------------------------------------------------------
extern "C" void kernel_launch(void* const* d_in, const int* in_sizes, int n_in,
                              void* d_out, int out_size) {
    const float* x  = (const float*)d_in[0];
    const float* h0 = (const float*)d_in[1];
    const float* Wr = (const float*)d_in[2];
    const float* br = (const float*)d_in[3];
    const float* Wz = (const float*)d_in[4];
    const float* bz = (const float*)d_in[5];
    const float* Wh = (const float*)d_in[6];
    const float* bh = (const float*)d_in[7];
    const float* Wo = (const float*)d_in[8];
    const float* bo = (const float*)d_in[9];
    float* out = (float*)d_out;

    long os = out_size;
    int Tfull = in_sizes[0] / (Bc * Ic);
    int Nt;
    bool with_h0;
    if (os > (long)Bc * Hc && ((os - (long)Bc * Hc) % ((long)Bc * Oc)) == 0) {
        Nt = (int)((os - (long)Bc * Hc) / ((long)Bc * Oc));
        with_h0 = true;
    } else {
        Nt = (int)(os / ((long)Bc * Oc));
        with_h0 = false;
    }
    int M = Bc * Nt;

    const int smemB = 3 * STGB;   // 110592 for all modes
    cudaFuncSetAttribute(kgemm<0>, cudaFuncAttributeMaxDynamicSharedMemorySize, smemB);
    cudaFuncSetAttribute(kgemm<1>, cudaFuncAttributeMaxDynamicSharedMemorySize, smemB);
    cudaFuncSetAttribute(kgemm<2>, cudaFuncAttributeMaxDynamicSharedMemorySize, smemB);

    __nv_bfloat16* wt;
    cudaGetSymbolAddress((void**)&wt, g_WT16);
    uint32_t* x16;
    cudaGetSymbolAddress((void**)&x16, g_x16);

    // Fused prep: transposes + hpart + h0 tail + x conversion, one launch
    long x4 = (long)in_sizes[0] / 4;
    int cvtPlanes = (int)((x4 + 262143) / 262144);
    float* h0dst = with_h0 ? (out + (long)M * Oc) : nullptr;
    prep_kernel<<<dim3(16, 16, 7 + cvtPlanes), dim3(32, 8)>>>(
        Wr, Wz, Wh, Wo, wt, h0, br, bz, h0dst, x, x16, x4);

    // GEMMs with programmatic dependent launch
    cudaLaunchAttribute attrs[1];
    attrs[0].id = cudaLaunchAttributeProgrammaticStreamSerialization;
    attrs[0].val.programmaticStreamSerializationAllowed = 1;

    cudaLaunchConfig_t cfg = {};
    cfg.blockDim = {256, 1, 1};
    cfg.dynamicSmemBytes = smemB;
    cfg.stream = 0;
    cfg.attrs = attrs;
    cfg.numAttrs = 1;

    float* nullf = nullptr;

    cfg.gridDim = {8, (unsigned)(M / 256), 1};   // 2-tile CTAs
    cudaLaunchKernelEx(&cfg, kgemm<0>, nullf, (const float*)nullptr, (const float*)nullptr, Nt, Tfull);

    cfg.gridDim = {4, (unsigned)(M / 128), 1};
    cudaLaunchKernelEx(&cfg, kgemm<1>, nullf, bh, h0, Nt, Tfull);

    cfg.gridDim = {4, (unsigned)(M / 256), 1};   // 2-tile CTAs
    cudaLaunchKernelEx(&cfg, kgemm<2>, out, bo, (const float*)nullptr, Nt, Tfull);
}

// round 17
// speedup vs baseline: 1.1494x; 1.1494x over previous
#include <cuda_runtime.h>
#include <cuda_bf16.h>
#include <cstdint>
#include <math.h>

#define Bc 64
#define Tc 512
#define Ic 512
#define Hc 512
#define Oc 512

// Scratch
__device__ uint32_t g_z16 [(long)Bc * Tc * Hc / 2];  // z (bf16x2)
__device__ uint32_t g_x16 [(long)Bc * Tc * Ic / 2];  // x as bf16x2
__device__ uint32_t g_zr16[(long)Bc * Tc * Hc / 2];  // zr (bf16x2)
__device__ uint32_t g_hn16[(long)Bc * Tc * Hc / 2];  // h_new (bf16x2)
__device__ float    g_hpr[Bc * Hc];
__device__ float    g_hpz[Bc * Hc];
__device__ __nv_bfloat16 g_WT16[5l * 512 * 512];     // W^T bf16 [sel][n][k]
// slabs: 0=Wr_x 1=Wz_x 2=Wh_x 3=Wh_h 4=Wo

__device__ __forceinline__ float sigmoidf_(float x) { return 1.0f / (1.0f + expf(-x)); }

__device__ __forceinline__ uint32_t pk(float lo, float hi) {
    __nv_bfloat162 h = __floats2bfloat162_rn(lo, hi);
    return *reinterpret_cast<uint32_t*>(&h);
}
__device__ __forceinline__ float2 upk(uint32_t u) {
    __nv_bfloat162 h = *reinterpret_cast<__nv_bfloat162*>(&u);
    return __bfloat1622float2(h);
}

__device__ __forceinline__ uint32_t smem_u32(const void* p) {
    uint32_t a;
    asm("{ .reg .u64 t; cvta.to.shared.u64 t, %1; cvt.u32.u64 %0, t; }" : "=r"(a) : "l"(p));
    return a;
}

__device__ __forceinline__ void gdc_wait()   { asm volatile("griddepcontrol.wait;" ::: "memory"); }
__device__ __forceinline__ void gdc_launch() { asm volatile("griddepcontrol.launch_dependents;" ::: "memory"); }

__device__ __forceinline__ void mma_bf16(float* c, const uint32_t* a, const uint32_t* b) {
    asm volatile(
        "mma.sync.aligned.m16n8k16.row.col.f32.bf16.bf16.f32 "
        "{%0,%1,%2,%3}, {%4,%5,%6,%7}, {%8,%9}, {%0,%1,%2,%3};"
        : "+f"(c[0]), "+f"(c[1]), "+f"(c[2]), "+f"(c[3])
        : "r"(a[0]), "r"(a[1]), "r"(a[2]), "r"(a[3]), "r"(b[0]), "r"(b[1]));
}

__device__ __forceinline__ void ldm4(uint32_t* r, uint32_t addr) {
    asm volatile("ldmatrix.sync.aligned.m8n8.x4.shared.b16 {%0,%1,%2,%3}, [%4];"
                 : "=r"(r[0]), "=r"(r[1]), "=r"(r[2]), "=r"(r[3]) : "r"(addr));
}

#define CP16(saddr, gptr) asm volatile("cp.async.cg.shared.global [%0], [%1], 16;" :: "r"(saddr), "l"(gptr))
#define CP_COMMIT()       asm volatile("cp.async.commit_group;" ::: "memory")
#define CP_WAIT1()        asm volatile("cp.async.wait_group 1;" ::: "memory")
#define CP_WAIT0()        asm volatile("cp.async.wait_group 0;" ::: "memory")

#define PITCH 36
#define ROWPB (PITCH * 4)                 // 144 bytes per row
#define STGB  (256u * ROWPB)              // bytes per stage (36864), all modes
#define WSLAB 524288                      // bytes per weight slab in g_WT16

// ---------------------------------------------------------------------------
// bf16 mma.sync GEMM (R13/R15 engine). ALL modes: 256 thr, 8 warps (4M x 2N),
// 2 CTAs/SM, CTA 128M x 128 B-rows, BK=64, cp.async 3-stage, ldmatrix x4.
//
// PDL schedule:
//   MODE 0: gdc_wait (needs prep) then gdc_launch IMMEDIATELY -> k1 CTAs
//           dispatch as k0 waves retire.
//   MODE 1: K=1024 REORDERED: chunks 0-7 = x@Wh_x (independent of k0, runs
//           pre-wait), gdc_wait at cc==6 (before first zr prefetch),
//           chunks 8-15 = zr@Wh_h. gdc_launch after mainloop.
//   MODE 2: B(Wo) prefetch pre-wait, gdc_wait, A(hn) issues; launch after main.
// ---------------------------------------------------------------------------
template <int MODE>
__global__ __launch_bounds__(256, 2)
void kgemm(float* __restrict__ Cout, const float* __restrict__ bias,
           const float* __restrict__ h0, int Nt, int Tfull)
{
    constexpr int CHUNKS = (MODE == 1) ? 16 : 8;
    constexpr int W      = (MODE == 0) ? 2 : 1;
    constexpr int NT     = (MODE == 0) ? 4 : 8;
    constexpr int NTILE  = (MODE == 0) ? 64 : 128;
    constexpr int WNW    = (MODE == 0) ? 32 : 64;
    constexpr int NCHT   = 8;

    extern __shared__ uint32_t sm[];
    const uint32_t sbase = smem_u32(sm);

    const int tid = threadIdx.x;
    const int wid = tid >> 5, lid = tid & 31;
    const int g = lid >> 2, t = lid & 3;
    const int warpM = wid & 3;
    const int warpN = wid >> 2;
    const int m0 = blockIdx.y * 128;
    const int n0 = blockIdx.x * NTILE;

    const char* xb  = (const char*)g_x16;
    const char* zrb = (const char*)g_zr16;
    const char* hnb = (const char*)g_hn16;
    const char* wtb = (const char*)g_WT16;

    uint32_t offP[NCHT];
    uint32_t offX[4];
    uint32_t sofb[NCHT];
#pragma unroll
    for (int i = 0; i < NCHT; i++) {
        int c = tid + 256 * i;
        if (i < 4) {
            int row = c >> 3, q = c & 7;
            int gm = m0 + row;
            uint32_t xoff = (uint32_t)((long)(gm / Nt) * Tfull + (gm % Nt)) * 1024u + q * 16;
            if (MODE == 0) offP[i] = xoff;
            else           offP[i] = (uint32_t)gm * 1024u + q * 16;
            if (MODE == 1) offX[i] = xoff;
            sofb[i] = (uint32_t)row * ROWPB + q * 16;
        } else {
            int c2 = c - 1024;
            int brow = c2 >> 3, q = c2 & 7;
            if (MODE == 0) {
                int sel = brow >> 6, nr = brow & 63;
                offP[i] = (uint32_t)sel * WSLAB + (uint32_t)(n0 + nr) * 1024u + q * 16;
            } else {
                offP[i] = (uint32_t)(n0 + brow) * 1024u + q * 16;
            }
            sofb[i] = (uint32_t)(128 + brow) * ROWPB + q * 16;
        }
    }

    const uint32_t a_addr = sbase + (uint32_t)(warpM * 32 + (lid & 15)) * ROWPB
                          + ((lid & 16) ? 16 : 0);
    const int b_row = ((lid & 16) ? 8 : 0) + (lid & 7);
    const uint32_t b_addr = sbase + (uint32_t)(128 + b_row) * ROWPB + ((lid & 8) ? 16 : 0);

    uint32_t bgrp_off[4];
#pragma unroll
    for (int gb = 0; gb < 4; gb++) {
        int base = (MODE == 0) ? ((gb >> 1) * 64 + warpN * 32 + (gb & 1) * 16)
                               : (warpN * 64 + gb * 16);
        bgrp_off[gb] = (uint32_t)base * ROWPB;
    }

    float c[W][2][NT][4];
#pragma unroll
    for (int w = 0; w < W; w++)
#pragma unroll
        for (int mt = 0; mt < 2; mt++)
#pragma unroll
            for (int nt = 0; nt < NT; nt++)
#pragma unroll
                for (int q = 0; q < 4; q++) c[w][mt][nt][q] = 0.0f;

    // MODE 1 chunk order: kt 0..7 = x@Wh_x (slab 2), kt 8..15 = zr@Wh_h (slab 3)
    auto issue = [&](int i, int kt, uint32_t stb) {
        const char* src;
        if (MODE == 0) {
            src = ((i < 4) ? xb : wtb) + offP[i] + kt * 128;
        } else if (MODE == 1) {
            if (i < 4) src = (kt < 8) ? (xb + offX[i < 4 ? i : 0] + kt * 128)
                                      : (zrb + offP[i] + (kt - 8) * 128);
            else       src = wtb + offP[i] + ((kt < 8) ? 2u : 3u) * WSLAB + (kt & 7) * 128;
        } else {
            src = ((i < 4) ? (hnb + offP[i]) : (wtb + offP[i] + 4u * WSLAB)) + kt * 128;
        }
        CP16(sbase + stb + sofb[i], src);
    };

    // ---- prologue ----
    if (MODE == 0) {
        gdc_wait();          // prep must be done (x16 + weights)
        gdc_launch();        // let k1 dispatch as our waves retire
#pragma unroll
        for (int i = 0; i < NCHT; i++) issue(i, 0, 0);
        CP_COMMIT();
#pragma unroll
        for (int i = 0; i < NCHT; i++) issue(i, 1, STGB);
        CP_COMMIT();
    } else if (MODE == 1) {
        // x-half is independent of k0: start immediately, no wait.
#pragma unroll
        for (int i = 0; i < NCHT; i++) issue(i, 0, 0);
        CP_COMMIT();
#pragma unroll
        for (int i = 0; i < NCHT; i++) issue(i, 1, STGB);
        CP_COMMIT();
    } else {
        // Weights (Wo) are >=2 PDL hops upstream: prefetch pre-wait.
#pragma unroll
        for (int i = 4; i < NCHT; i++) issue(i, 0, 0);
#pragma unroll
        for (int i = 4; i < NCHT; i++) issue(i, 1, STGB);
        gdc_wait();
#pragma unroll
        for (int i = 0; i < 4; i++) issue(i, 0, 0);
        CP_COMMIT();          // group0 = {B ch0, B ch1, A ch0}
#pragma unroll
        for (int i = 0; i < 4; i++) issue(i, 1, STGB);
        CP_COMMIT();          // group1 = {A ch1}
    }
    CP_WAIT1();
    __syncthreads();

    // ---- mainloop ----
    for (int kt = 0; kt < CHUNKS; kt++) {
        const uint32_t stb = (uint32_t)(kt % 3) * STGB;
        const bool pf = (kt < CHUNKS - 2);
        const uint32_t nstb = (uint32_t)((kt + 2) % 3) * STGB;

        // MODE 1: first zr chunk (8) gets prefetched at kt==6 -> wait for k0.
        if (MODE == 1 && kt == 6) gdc_wait();

#pragma unroll
        for (int ks = 0; ks < 4; ks++) {
            if (pf) { issue(2 * ks, kt + 2, nstb); issue(2 * ks + 1, kt + 2, nstb); }
            uint32_t af4[2][4];
#pragma unroll
            for (int mt = 0; mt < 2; mt++)
                ldm4(af4[mt], a_addr + stb + (uint32_t)mt * (16 * ROWPB) + ks * 32);
            uint32_t bf4[4][4];
#pragma unroll
            for (int gb = 0; gb < 4; gb++)
                ldm4(bf4[gb], b_addr + stb + bgrp_off[gb] + ks * 32);

            if (MODE == 0) {
#pragma unroll
                for (int w = 0; w < 2; w++)
#pragma unroll
                    for (int mt = 0; mt < 2; mt++)
#pragma unroll
                        for (int nt = 0; nt < NT; nt++)
                            mma_bf16(c[w % W][mt][nt], af4[mt],
                                     &bf4[w * 2 + (nt >> 1)][(nt & 1) * 2]);
            } else {
#pragma unroll
                for (int mt = 0; mt < 2; mt++)
#pragma unroll
                    for (int nt = 0; nt < NT; nt++)
                        mma_bf16(c[0][mt][nt], af4[mt], &bf4[nt >> 1][(nt & 1) * 2]);
            }
        }

        if (pf) CP_COMMIT();
        if (kt < CHUNKS - 1) {
            if (pf) CP_WAIT1(); else CP_WAIT0();
            __syncthreads();
        }
    }

    if (MODE != 0) gdc_launch();

    // ---- epilogue ----
#pragma unroll
    for (int mt = 0; mt < 2; mt++) {
#pragma unroll
        for (int rh = 0; rh < 2; rh++) {
            const int m = m0 + warpM * 32 + mt * 16 + g + rh * 8;
            const int b = m / Nt;
#pragma unroll
            for (int nt = 0; nt < NT; nt++) {
                const int n = n0 + warpN * WNW + nt * 8 + t * 2;
                const long hidx = (long)m * 256 + (n >> 1);
                if (MODE == 0) {
                    float vr0 = c[0][mt][nt][rh * 2 + 0], vr1 = c[0][mt][nt][rh * 2 + 1];
                    float vz0 = c[1 % W][mt][nt][rh * 2 + 0], vz1 = c[1 % W][mt][nt][rh * 2 + 1];
                    float r0 = sigmoidf_(vr0 + g_hpr[b * 512 + n]);
                    float r1 = sigmoidf_(vr1 + g_hpr[b * 512 + n + 1]);
                    float z0 = sigmoidf_(vz0 + g_hpz[b * 512 + n]);
                    float z1 = sigmoidf_(vz1 + g_hpz[b * 512 + n + 1]);
                    g_zr16[hidx] = pk(z0 * r0, z1 * r1);
                    g_z16[hidx]  = pk(z0, z1);
                } else if (MODE == 1) {
                    float v0 = c[0][mt][nt][rh * 2 + 0], v1 = c[0][mt][nt][rh * 2 + 1];
                    float2 zv = upk(g_z16[hidx]);
                    float2 hv = *(const float2*)(h0 + b * 512 + n);
                    float2 bv = *(const float2*)(bias + n);
                    float o0 = (1.0f - zv.x) * hv.x + zv.x * tanhf(v0 + bv.x);
                    float o1 = (1.0f - zv.y) * hv.y + zv.y * tanhf(v1 + bv.y);
                    g_hn16[hidx] = pk(o0, o1);
                } else {
                    float v0 = c[0][mt][nt][rh * 2 + 0], v1 = c[0][mt][nt][rh * 2 + 1];
                    float2 bv = *(const float2*)(bias + n);
                    *(float2*)(Cout + (long)m * 512 + n) =
                        make_float2(sigmoidf_(v0 + bv.x), sigmoidf_(v1 + bv.y));
                }
            }
        }
    }
}

// ---------------------------------------------------------------------------
// Fused prep kernel: blockIdx.z selects work.
//   z = 0..4  : transpose+cvt weight sel z into g_WT16
//   z = 5     : hpart (g_hpr/g_hpz), first 128 of 256 blocks
//   z = 6     : copy h0 -> out tail (if h0dst != null), first 128 blocks
//   z >= 7    : x fp32 -> bf16x2 conversion
// ---------------------------------------------------------------------------
__global__ void prep_kernel(const float* __restrict__ Wr, const float* __restrict__ Wz,
                            const float* __restrict__ Wh, const float* __restrict__ Wo,
                            __nv_bfloat16* __restrict__ wdst,
                            const float* __restrict__ h0,
                            const float* __restrict__ br, const float* __restrict__ bz,
                            float* __restrict__ h0dst,
                            const float* __restrict__ x, uint32_t* __restrict__ x16,
                            long x4) {
    const int z = blockIdx.z;
    if (z < 5) {
        __shared__ float tbuf[32][33];
        const float* src = (z == 0) ? Wr : (z == 1) ? Wz : (z == 2) ? Wh
                         : (z == 3) ? (Wh + (long)Ic * Hc) : Wo;
        __nv_bfloat16* d = wdst + (long)z * 512 * 512;
        int bx = blockIdx.x * 32, by = blockIdx.y * 32;
#pragma unroll
        for (int i = 0; i < 4; i++)
            tbuf[threadIdx.y + i * 8][threadIdx.x] =
                src[(long)(by + threadIdx.y + i * 8) * 512 + bx + threadIdx.x];
        __syncthreads();
#pragma unroll
        for (int i = 0; i < 4; i++)
            d[(long)(bx + threadIdx.y + i * 8) * 512 + by + threadIdx.x] =
                __float2bfloat16(tbuf[threadIdx.x][threadIdx.y + i * 8]);
        gdc_launch();
        return;
    }
    const int tid = threadIdx.y * 32 + threadIdx.x;          // 0..255
    const int bid = blockIdx.y * 16 + blockIdx.x;            // 0..255
    if (z == 5) {
        if (bid < 128) {
            const int idx = bid * 256 + tid;
            const int b = idx >> 9, n = idx & 511;
            const float* Wr_h = Wr + (long)Ic * Hc;
            const float* Wz_h = Wz + (long)Ic * Hc;
            float ar = br[n], az = bz[n];
            const float* h0b = h0 + b * Hc;
            for (int k = 0; k < Hc; k++) {
                float h = h0b[k];
                ar = fmaf(h, Wr_h[k * Hc + n], ar);
                az = fmaf(h, Wz_h[k * Hc + n], az);
            }
            g_hpr[idx] = ar;
            g_hpz[idx] = az;
        }
    } else if (z == 6) {
        if (bid < 128 && h0dst) {
            const int idx = bid * 256 + tid;
            h0dst[idx] = h0[idx];
        }
    } else {
        const long base = ((long)(z - 7) * 256 + bid) * 1024;
#pragma unroll
        for (int it = 0; it < 4; it++) {
            long i = base + it * 256 + tid;
            if (i < x4) {
                float4 v = ((const float4*)x)[i];
                ((uint2*)x16)[i] = make_uint2(pk(v.x, v.y), pk(v.z, v.w));
            }
        }
    }
    gdc_launch();
}

// ---------------------------------------------------------------------------
extern "C" void kernel_launch(void* const* d_in, const int* in_sizes, int n_in,
                              void* d_out, int out_size) {
    const float* x  = (const float*)d_in[0];
    const float* h0 = (const float*)d_in[1];
    const float* Wr = (const float*)d_in[2];
    const float* br = (const float*)d_in[3];
    const float* Wz = (const float*)d_in[4];
    const float* bz = (const float*)d_in[5];
    const float* Wh = (const float*)d_in[6];
    const float* bh = (const float*)d_in[7];
    const float* Wo = (const float*)d_in[8];
    const float* bo = (const float*)d_in[9];
    float* out = (float*)d_out;

    long os = out_size;
    int Tfull = in_sizes[0] / (Bc * Ic);
    int Nt;
    bool with_h0;
    if (os > (long)Bc * Hc && ((os - (long)Bc * Hc) % ((long)Bc * Oc)) == 0) {
        Nt = (int)((os - (long)Bc * Hc) / ((long)Bc * Oc));
        with_h0 = true;
    } else {
        Nt = (int)(os / ((long)Bc * Oc));
        with_h0 = false;
    }
    int M = Bc * Nt;

    const int smemB = 3 * STGB;   // 110592 for all modes
    cudaFuncSetAttribute(kgemm<0>, cudaFuncAttributeMaxDynamicSharedMemorySize, smemB);
    cudaFuncSetAttribute(kgemm<1>, cudaFuncAttributeMaxDynamicSharedMemorySize, smemB);
    cudaFuncSetAttribute(kgemm<2>, cudaFuncAttributeMaxDynamicSharedMemorySize, smemB);

    __nv_bfloat16* wt;
    cudaGetSymbolAddress((void**)&wt, g_WT16);
    uint32_t* x16;
    cudaGetSymbolAddress((void**)&x16, g_x16);

    // Fused prep: transposes + hpart + h0 tail + x conversion, one launch
    long x4 = (long)in_sizes[0] / 4;
    int cvtPlanes = (int)((x4 + 262143) / 262144);
    float* h0dst = with_h0 ? (out + (long)M * Oc) : nullptr;
    prep_kernel<<<dim3(16, 16, 7 + cvtPlanes), dim3(32, 8)>>>(
        Wr, Wz, Wh, Wo, wt, h0, br, bz, h0dst, x, x16, x4);

    // GEMMs with programmatic dependent launch
    cudaLaunchAttribute attrs[1];
    attrs[0].id = cudaLaunchAttributeProgrammaticStreamSerialization;
    attrs[0].val.programmaticStreamSerializationAllowed = 1;

    cudaLaunchConfig_t cfg = {};
    cfg.blockDim = {256, 1, 1};
    cfg.dynamicSmemBytes = smemB;
    cfg.stream = 0;
    cfg.attrs = attrs;
    cfg.numAttrs = 1;

    float* nullf = nullptr;

    cfg.gridDim = {8, (unsigned)(M / 128), 1};
    cudaLaunchKernelEx(&cfg, kgemm<0>, nullf, (const float*)nullptr, (const float*)nullptr, Nt, Tfull);

    cfg.gridDim = {4, (unsigned)(M / 128), 1};
    cudaLaunchKernelEx(&cfg, kgemm<1>, nullf, bh, h0, Nt, Tfull);

    cfg.gridDim = {4, (unsigned)(M / 128), 1};
    cudaLaunchKernelEx(&cfg, kgemm<2>, out, bo, (const float*)nullptr, Nt, Tfull);
}